// round 6
// baseline (speedup 1.0000x reference)
#include <cuda_runtime.h>
#include <cuda_fp16.h>

#define NBX 168
#define NBY 480
#define NBL 6
#define NBXP (NBX + 4)                // x-padded rows (+2 guard each side)
#define NBYP 496                      // padded y stride (halfs/floats)
#define PADY 8                        // y guard offset
#define PLANE (NBXP * NBYP)           // 85312
#define NDEM (NBL * PLANE)            // 511872
#define WW 5
#define INV_SQRT2 0.70710678118654752440f
#define INV_CAP (1.0f / 16.0f)

__device__ __align__(16) float  g_dem[NDEM];
__device__ __align__(16) __half g_compatA[NDEM];   // value at slot y
__device__ __align__(16) __half g_compatB[NDEM];   // B[y'] = A[y'+4]

__device__ __forceinline__ void red_add_v4(float* addr, float a, float b,
                                           float c, float d) {
    asm volatile("red.global.add.v4.f32 [%0], {%1, %2, %3, %4};"
                 :: "l"(addr), "f"(a), "f"(b), "f"(c), "f"(d) : "memory");
}

// Fast erf (Abramowitz-Stegun 7.1.26, |abs err| <= 1.5e-7): 2 MUFU + ~9 FMA.
__device__ __forceinline__ float erf_fast(float x) {
    float ax = fabsf(x);
    float t = __fdividef(1.0f, fmaf(0.3275911f, ax, 1.0f));
    float e = __expf(-ax * ax);
    float q = fmaf(1.061405429f, t, -1.453152027f);
    q = fmaf(q, t, 1.421413741f);
    q = fmaf(q, t, -0.284496736f);
    q = fmaf(q, t, 0.254829592f);
    float r = fmaf(-q * t, e, 1.0f);
    return copysignf(r, x);
}

// ---------------------------------------------------------------------------
// Phase 0: zero demand map, compatB tails, output buffer
// ---------------------------------------------------------------------------
__global__ void zero_kernel(float* __restrict__ out, int out_n) {
    int i = blockIdx.x * blockDim.x + threadIdx.x;
    if (i < NDEM) g_dem[i] = 0.0f;
    if (i < NDEM / 2) ((unsigned*)g_compatB)[i] = 0u;
    if (i < out_n) out[i] = 0.0f;
}

// 5-wide x-axis weights, NO range mask (OOB mass goes to pad rows / is
// masked by the caller).
__device__ __forceinline__ void wx5(float c, int& b0, float* g) {
    b0 = (int)floorf(c) - 2;
    float ep = erf_fast(((float)b0 - c) * INV_SQRT2);
#pragma unroll
    for (int k = 0; k < WW; k++) {
        float e = erf_fast(((float)(b0 + k + 1) - c) * INV_SQRT2);
        g[k] = 0.5f * (e - ep);
        ep = e;
    }
}

// 8 aligned y slots (y4 = 4-aligned). Window-truncation mask always applied;
// RANGE adds the [0,NBY) mask (needed on the gather side only).
template <bool RANGE>
__device__ __forceinline__ void wy8(float c, int& y4, float* w) {
    int b0 = (int)floorf(c) - 2;
    y4 = b0 & ~3;
    int m = b0 - y4;                  // 0..3
    float ep = erf_fast(((float)y4 - c) * INV_SQRT2);
#pragma unroll
    for (int s = 0; s < 8; s++) {
        float e = erf_fast(((float)(y4 + s + 1) - c) * INV_SQRT2);
        bool ok = ((unsigned)(s - m) <= 4u);
        if (RANGE) ok = ok && ((unsigned)(y4 + s) < NBY);
        w[s] = ok ? 0.5f * (e - ep) : 0.0f;
        ep = e;
    }
}

// ---------------------------------------------------------------------------
// Phase 1: scatter-add, 10 unconditional RED.v4 per instance
// ---------------------------------------------------------------------------
__global__ void scatter_kernel(const float* __restrict__ pos,
                               const float* __restrict__ nsx,
                               const float* __restrict__ nsy,
                               const int*   __restrict__ lidx,
                               const int*   __restrict__ ltype,
                               int Lnum, int n) {
    int l = blockIdx.x * blockDim.x + threadIdx.x;
    if (l >= Lnum) return;
    int idx = lidx[l];
    float sx = nsx[idx];
    float sy = nsy[idx];
    float cx = pos[idx]     + 0.5f * sx;
    float cy = pos[n + idx] + 0.5f * sy;
    float area = sx * sy;
    int lt = ltype[idx];

    int bx0, y4;
    float wx[WW], wy[8];
    wx5(cx, bx0, wx);
    wy8<false>(cy, y4, wy);

    float* p = g_dem + ((lt * NBXP + (bx0 + 2)) * NBYP + PADY + y4);
#pragma unroll
    for (int i = 0; i < WW; i++) {
        float axi = area * wx[i];
        red_add_v4(p,     axi * wy[0], axi * wy[1], axi * wy[2], axi * wy[3]);
        red_add_v4(p + 4, axi * wy[4], axi * wy[5], axi * wy[6], axi * wy[7]);
        p += NBYP;
    }
}

// ---------------------------------------------------------------------------
// Phase 2: compat[t,x,y] = sum_l frac[t,l] * dem[l,x,y] -> fp16, two copies
// ---------------------------------------------------------------------------
__global__ void compat_kernel(const int* __restrict__ frac) {
    int p = blockIdx.x * blockDim.x + threadIdx.x;
    if (p >= PLANE) return;
    int ymod = p % NBYP;
    float d[NBL];
#pragma unroll
    for (int l = 0; l < NBL; l++) d[l] = g_dem[l * PLANE + p];
#pragma unroll
    for (int t = 0; t < NBL; t++) {
        float s = 0.0f;
#pragma unroll
        for (int l = 0; l < NBL; l++)
            s += (float)__ldg(&frac[t * NBL + l]) * d[l];
        __half h = __float2half_rn(s);
        g_compatA[t * PLANE + p] = h;
        if (ymod >= 4) g_compatB[t * PLANE + p - 4] = h;
    }
}

// ---------------------------------------------------------------------------
// Phase 3: gather fp16 compat, one LDG.128 per x-row
// ---------------------------------------------------------------------------
__global__ void gather_kernel(const float* __restrict__ pos,
                              const float* __restrict__ nsx,
                              const float* __restrict__ nsy,
                              const int*   __restrict__ lidx,
                              const int*   __restrict__ ltype,
                              float* __restrict__ out,
                              int Lnum, int n) {
    int l = blockIdx.x * blockDim.x + threadIdx.x;
    if (l >= Lnum) return;
    int idx = lidx[l];
    float sx = nsx[idx];
    float sy = nsy[idx];
    float cx = pos[idx]     + 0.5f * sx;
    float cy = pos[n + idx] + 0.5f * sy;
    int lt = ltype[idx];

    int bx0, y4;
    float wx[WW], wy[8];
    wx5(cx, bx0, wx);
    wy8<true>(cy, y4, wy);

    // zero OOB x weights (pad rows hold scatter spill, must not contribute)
#pragma unroll
    for (int i = 0; i < WW; i++)
        if ((unsigned)(bx0 + i) >= (unsigned)NBX) wx[i] = 0.0f;

    // Pick the copy where the 8-half window is 16B-aligned.
    const __half* map;
    int slot;
    if (y4 & 4) { map = g_compatB; slot = y4 - 4; }
    else        { map = g_compatA; slot = y4;     }
    const __half* base = map + ((lt * NBXP + (bx0 + 2)) * NBYP + PADY + slot);

    uint4 v[WW];
#pragma unroll
    for (int i = 0; i < WW; i++)
        v[i] = *(const uint4*)(base + i * NBYP);

    float s = 0.0f;
#pragma unroll
    for (int i = 0; i < WW; i++) {
        float2 c0 = __half22float2(*(const __half2*)&v[i].x);
        float2 c1 = __half22float2(*(const __half2*)&v[i].y);
        float2 c2 = __half22float2(*(const __half2*)&v[i].z);
        float2 c3 = __half22float2(*(const __half2*)&v[i].w);
        float sj = c0.x * wy[0] + c0.y * wy[1] + c1.x * wy[2] + c1.y * wy[3]
                 + c2.x * wy[4] + c2.y * wy[5] + c3.x * wy[6] + c3.y * wy[7];
        s += wx[i] * sj;
    }
    out[idx] = s * INV_CAP;
}

// ---------------------------------------------------------------------------
extern "C" void kernel_launch(void* const* d_in, const int* in_sizes, int n_in,
                              void* d_out, int out_size) {
    const float* pos   = (const float*)d_in[0];
    const float* nsx   = (const float*)d_in[1];
    const float* nsy   = (const float*)d_in[2];
    const int*   lidx  = (const int*)d_in[3];
    const int*   ltype = (const int*)d_in[4];
    const int*   frac  = (const int*)d_in[5];
    float* out = (float*)d_out;

    int n    = in_sizes[1];   // number of nodes (2M)
    int Lnum = in_sizes[3];   // number of instances (1M)

    {
        int tot = out_size > NDEM ? out_size : NDEM;
        zero_kernel<<<(tot + 255) / 256, 256>>>(out, out_size);
    }
    scatter_kernel<<<(Lnum + 255) / 256, 256>>>(pos, nsx, nsy, lidx, ltype,
                                                Lnum, n);
    compat_kernel<<<(PLANE + 255) / 256, 256>>>(frac);
    gather_kernel<<<(Lnum + 255) / 256, 256>>>(pos, nsx, nsy, lidx, ltype,
                                               out, Lnum, n);
}

// round 7
// speedup vs baseline: 1.4441x; 1.4441x over previous
#include <cuda_runtime.h>
#include <cuda_fp16.h>

#define NBX 168
#define NBY 480
#define NBL 6
#define NBXP (NBX + 4)                // x-padded rows (+2 guard each side)
#define NBYP 496                      // padded y stride in halfs (mult of 8)
#define PADY 8                        // y guard offset (mult of 8)
#define PLANE (NBXP * NBYP)           // 85312 (mult of 4)
#define NDEM (NBL * PLANE)            // 511872 (mult of 8)
#define NREP 4                        // fp16 accumulation replicas
#define QROW (NBYP / 4)               // 124 quads per row
#define NQ (PLANE / 4)                // 21328
#define WW 5
#define INV_SQRT2 0.70710678118654752440f
#define INV_CAP (1.0f / 16.0f)

// Demand: fp16, 4 replicas x 2 shift variants. A[h] = slot h; B[h] = slot h+4.
__device__ __align__(16) __half g_demA[NREP][NDEM];
__device__ __align__(16) __half g_demB[NREP][NDEM];
// Compat: fp16, two shifted copies (A at slot h, B[h] = A[h+4]).
__device__ __align__(16) __half g_compatA[NDEM];
__device__ __align__(16) __half g_compatB[NDEM];

__device__ __forceinline__ void red_add_v4h2(__half* addr, __half2 a, __half2 b,
                                             __half2 c, __half2 d) {
    unsigned ua = *(unsigned*)&a, ub = *(unsigned*)&b;
    unsigned uc = *(unsigned*)&c, ud = *(unsigned*)&d;
    asm volatile("red.global.add.noftz.v4.f16x2 [%0], {%1, %2, %3, %4};"
                 :: "l"(addr), "r"(ua), "r"(ub), "r"(uc), "r"(ud) : "memory");
}

// Fast erf (Abramowitz-Stegun 7.1.26, |abs err| <= 1.5e-7).
__device__ __forceinline__ float erf_fast(float x) {
    float ax = fabsf(x);
    float t = __fdividef(1.0f, fmaf(0.3275911f, ax, 1.0f));
    float e = __expf(-ax * ax);
    float q = fmaf(1.061405429f, t, -1.453152027f);
    q = fmaf(q, t, 1.421413741f);
    q = fmaf(q, t, -0.284496736f);
    q = fmaf(q, t, 0.254829592f);
    float r = fmaf(-q * t, e, 1.0f);
    return copysignf(r, x);
}

// 5-wide x-axis weights, no range mask (spill goes to pad rows).
__device__ __forceinline__ void wx5(float c, int& b0, float* g) {
    b0 = (int)floorf(c) - 2;
    float ep = erf_fast(((float)b0 - c) * INV_SQRT2);
#pragma unroll
    for (int k = 0; k < WW; k++) {
        float e = erf_fast(((float)(b0 + k + 1) - c) * INV_SQRT2);
        g[k] = 0.5f * (e - ep);
        ep = e;
    }
}

// 8 slots at 4-aligned y4. Window-truncation mask always; RANGE adds [0,NBY).
template <bool RANGE>
__device__ __forceinline__ void wy8(float c, int& y4, float* w) {
    int b0 = (int)floorf(c) - 2;
    y4 = b0 & ~3;
    int m = b0 - y4;                  // 0..3
    float ep = erf_fast(((float)y4 - c) * INV_SQRT2);
#pragma unroll
    for (int s = 0; s < 8; s++) {
        float e = erf_fast(((float)(y4 + s + 1) - c) * INV_SQRT2);
        bool ok = ((unsigned)(s - m) <= 4u);
        if (RANGE) ok = ok && ((unsigned)(y4 + s) < NBY);
        w[s] = ok ? 0.5f * (e - ep) : 0.0f;
        ep = e;
    }
}

// ---------------------------------------------------------------------------
// Phase 1: scatter — 5 x v4.f16x2 REDs per instance. Also zeroes the output.
// ---------------------------------------------------------------------------
__global__ void scatter_kernel(const float* __restrict__ pos,
                               const float* __restrict__ nsx,
                               const float* __restrict__ nsy,
                               const int*   __restrict__ lidx,
                               const int*   __restrict__ ltype,
                               float* __restrict__ out, int osz,
                               int Lnum, int n) {
    int l = blockIdx.x * blockDim.x + threadIdx.x;
    int nt = gridDim.x * blockDim.x;
    // Zero the output buffer (gather overwrites the touched entries later).
    for (int i = l; i * 2 + 1 < osz; i += nt)
        ((float2*)out)[i] = make_float2(0.0f, 0.0f);
    if (l == 0 && (osz & 1)) out[osz - 1] = 0.0f;

    if (l >= Lnum) return;
    int idx = lidx[l];
    float sx = nsx[idx];
    float sy = nsy[idx];
    float cx = pos[idx]     + 0.5f * sx;
    float cy = pos[n + idx] + 0.5f * sy;
    float area = sx * sy;
    int lt = ltype[idx];
    int rep = l & (NREP - 1);

    int bx0, y4;
    float wx[WW], wy[8];
    wx5(cx, bx0, wx);
    wy8<false>(cy, y4, wy);

    __half2 hwy[4];
    hwy[0] = __floats2half2_rn(wy[0], wy[1]);
    hwy[1] = __floats2half2_rn(wy[2], wy[3]);
    hwy[2] = __floats2half2_rn(wy[4], wy[5]);
    hwy[3] = __floats2half2_rn(wy[6], wy[7]);

    __half* base;
    int h0;
    if (y4 & 4) { base = g_demB[rep]; h0 = PADY + y4 - 4; }
    else        { base = g_demA[rep]; h0 = PADY + y4;     }
    base += (lt * NBXP + bx0 + 2) * NBYP + h0;

#pragma unroll
    for (int i = 0; i < WW; i++) {
        __half2 a2 = __half2half2(__float2half_rn(area * wx[i]));
        red_add_v4h2(base, __hmul2(a2, hwy[0]), __hmul2(a2, hwy[1]),
                           __hmul2(a2, hwy[2]), __hmul2(a2, hwy[3]));
        base += NBYP;
    }
}

// ---------------------------------------------------------------------------
// Phase 2: compat = frac * dem (replicas + shift variants summed in fp32),
// written as fp16 into two shifted copies. One thread per 4-half quad.
// ---------------------------------------------------------------------------
__device__ __forceinline__ float4 acc_quad(float4 a, uint2 v) {
    float2 f0 = __half22float2(*(const __half2*)&v.x);
    float2 f1 = __half22float2(*(const __half2*)&v.y);
    a.x += f0.x; a.y += f0.y; a.z += f1.x; a.w += f1.y;
    return a;
}

__global__ void compat_kernel(const int* __restrict__ frac) {
    int q = blockIdx.x * blockDim.x + threadIdx.x;
    if (q >= NQ) return;
    int qr = q % QROW;

    float4 d[NBL];
#pragma unroll
    for (int l = 0; l < NBL; l++) {
        float4 acc = make_float4(0.f, 0.f, 0.f, 0.f);
#pragma unroll
        for (int r = 0; r < NREP; r++)
            acc = acc_quad(acc, *(const uint2*)&g_demA[r][l * PLANE + q * 4]);
        if (qr > 0) {
#pragma unroll
            for (int r = 0; r < NREP; r++)
                acc = acc_quad(acc, *(const uint2*)&g_demB[r][l * PLANE + (q - 1) * 4]);
        }
        d[l] = acc;
    }

#pragma unroll
    for (int t = 0; t < NBL; t++) {
        float4 s = make_float4(0.f, 0.f, 0.f, 0.f);
#pragma unroll
        for (int l = 0; l < NBL; l++) {
            float f = (float)__ldg(&frac[t * NBL + l]);
            s.x = fmaf(f, d[l].x, s.x);
            s.y = fmaf(f, d[l].y, s.y);
            s.z = fmaf(f, d[l].z, s.z);
            s.w = fmaf(f, d[l].w, s.w);
        }
        __half2 h0 = __floats2half2_rn(s.x, s.y);
        __half2 h1 = __floats2half2_rn(s.z, s.w);
        uint2 o;
        o.x = *(unsigned*)&h0;
        o.y = *(unsigned*)&h1;
        *(uint2*)&g_compatA[t * PLANE + q * 4] = o;
        if (qr > 0)
            *(uint2*)&g_compatB[t * PLANE + (q - 1) * 4] = o;
    }
}

// ---------------------------------------------------------------------------
// Phase 3: gather fp16 compat (one LDG.128 per x-row) + zero dem for the
// next replay (compat has already consumed it).
// ---------------------------------------------------------------------------
__global__ void gather_kernel(const float* __restrict__ pos,
                              const float* __restrict__ nsx,
                              const float* __restrict__ nsy,
                              const int*   __restrict__ lidx,
                              const int*   __restrict__ ltype,
                              float* __restrict__ out,
                              int Lnum, int n) {
    int l = blockIdx.x * blockDim.x + threadIdx.x;
    int nt = gridDim.x * blockDim.x;
    // Zero demand replicas for the next replay (8B per thread-step).
    const int NZ = NREP * NDEM / 4;
    for (int i = l; i < NZ; i += nt) {
        ((uint2*)g_demA)[i] = make_uint2(0u, 0u);
        ((uint2*)g_demB)[i] = make_uint2(0u, 0u);
    }

    if (l >= Lnum) return;
    int idx = lidx[l];
    float sx = nsx[idx];
    float sy = nsy[idx];
    float cx = pos[idx]     + 0.5f * sx;
    float cy = pos[n + idx] + 0.5f * sy;
    int lt = ltype[idx];

    int bx0, y4;
    float wx[WW], wy[8];
    wx5(cx, bx0, wx);
    wy8<true>(cy, y4, wy);

    // zero OOB x weights (pad rows hold scatter spill, must not contribute)
#pragma unroll
    for (int i = 0; i < WW; i++)
        if ((unsigned)(bx0 + i) >= (unsigned)NBX) wx[i] = 0.0f;

    const __half* map;
    int slot;
    if (y4 & 4) { map = g_compatB; slot = y4 - 4; }
    else        { map = g_compatA; slot = y4;     }
    const __half* base = map + ((lt * NBXP + bx0 + 2) * NBYP + PADY + slot);

    uint4 v[WW];
#pragma unroll
    for (int i = 0; i < WW; i++)
        v[i] = *(const uint4*)(base + i * NBYP);

    float s = 0.0f;
#pragma unroll
    for (int i = 0; i < WW; i++) {
        float2 c0 = __half22float2(*(const __half2*)&v[i].x);
        float2 c1 = __half22float2(*(const __half2*)&v[i].y);
        float2 c2 = __half22float2(*(const __half2*)&v[i].z);
        float2 c3 = __half22float2(*(const __half2*)&v[i].w);
        float sj = c0.x * wy[0] + c0.y * wy[1] + c1.x * wy[2] + c1.y * wy[3]
                 + c2.x * wy[4] + c2.y * wy[5] + c3.x * wy[6] + c3.y * wy[7];
        s += wx[i] * sj;
    }
    out[idx] = s * INV_CAP;
}

// ---------------------------------------------------------------------------
extern "C" void kernel_launch(void* const* d_in, const int* in_sizes, int n_in,
                              void* d_out, int out_size) {
    const float* pos   = (const float*)d_in[0];
    const float* nsx   = (const float*)d_in[1];
    const float* nsy   = (const float*)d_in[2];
    const int*   lidx  = (const int*)d_in[3];
    const int*   ltype = (const int*)d_in[4];
    const int*   frac  = (const int*)d_in[5];
    float* out = (float*)d_out;

    int n    = in_sizes[1];   // number of nodes (2M)
    int Lnum = in_sizes[3];   // number of instances (1M)

    scatter_kernel<<<(Lnum + 255) / 256, 256>>>(pos, nsx, nsy, lidx, ltype,
                                                out, out_size, Lnum, n);
    compat_kernel<<<(NQ + 255) / 256, 256>>>(frac);
    gather_kernel<<<(Lnum + 255) / 256, 256>>>(pos, nsx, nsy, lidx, ltype,
                                               out, Lnum, n);
}